// round 4
// baseline (speedup 1.0000x reference)
#include <cuda_runtime.h>
#include <math.h>
#include <float.h>

// AUAvULoss: N=65536 rows, C=1000 classes fp32 logits, int64 labels.
// K1 (k_rows): one WARP per row -> g_unc / g_confacc, fused per-block
//              min/max(unc) + sum(ce) global atomics.
// K2 (k_bins): cutoff-index histogram into 88 bins; LAST block computes
//              the final scalar (completion-counter fusion).

#define MAXN 65536

__device__ float g_unc[MAXN];
__device__ float g_confacc[MAXN];   // +conf if accurate, -conf if not
__device__ unsigned int g_umin_bits;
__device__ unsigned int g_umax_bits;
__device__ float g_cesum;
__device__ unsigned int g_done;
// layout: [acc(0/1)][kind(0=certain,1=uncertain)][j0 in 0..21]
__device__ float g_bins[88];

__device__ __forceinline__ unsigned int f2ord(float f) {
    unsigned int u = __float_as_uint(f);
    return (u & 0x80000000u) ? ~u : (u | 0x80000000u);
}
__device__ __forceinline__ float ord2f(unsigned int u) {
    return __uint_as_float((u & 0x80000000u) ? (u ^ 0x80000000u) : ~u);
}

__global__ void k_init() {
    int t = threadIdx.x;
    if (t < 88) g_bins[t] = 0.0f;
    if (t == 0) {
        g_umin_bits = 0xFFFFFFFFu;
        g_umax_bits = 0u;
        g_cesum = 0.0f;
        g_done = 0u;
    }
}

// ---------------- K1: one warp per row, fused stats reduction ----------------
template <int WPB>   // warps per block
__global__ void __launch_bounds__(WPB * 32)
k_rows(const float* __restrict__ logits,
       const long long* __restrict__ labels,
       int C, int n) {
    const int wid  = threadIdx.x >> 5;
    const int lane = threadIdx.x & 31;
    const int row  = blockIdx.x * WPB + wid;
    const bool active = (row < n);

    __shared__ float s_unc[WPB];
    __shared__ float s_ce[WPB];

    if (active) {
        const int chunks = (C + 3) >> 2;          // 250 for C=1000
        const float4* __restrict__ rp =
            reinterpret_cast<const float4*>(logits + (size_t)row * (size_t)C);

        // ---- front-batched loads: up to 8 float4 per lane ----
        float4 v[8];
        bool   ok[8];
        #pragma unroll
        for (int k = 0; k < 8; k++) {
            int c = lane + (k << 5);
            ok[k] = (c < chunks);
            if (ok[k]) v[k] = rp[c];
        }

        // ---- local max + first-index argmax ----
        float m = -FLT_MAX;
        int mi = 0x7FFFFFFF;
        #pragma unroll
        for (int k = 0; k < 8; k++) {
            if (ok[k]) {
                int base = (lane + (k << 5)) << 2;
                if (v[k].x > m) { m = v[k].x; mi = base; }
                if (v[k].y > m) { m = v[k].y; mi = base + 1; }
                if (v[k].z > m) { m = v[k].z; mi = base + 2; }
                if (v[k].w > m) { m = v[k].w; mi = base + 3; }
            }
        }
        #pragma unroll
        for (int o = 16; o > 0; o >>= 1) {
            float om = __shfl_xor_sync(0xffffffffu, m, o);
            int   oi = __shfl_xor_sync(0xffffffffu, mi, o);
            if (om > m || (om == m && oi < mi)) { m = om; mi = oi; }
        }
        const float rm = m;
        const int pred = mi;

        // ---- S = sum e^d, T = sum d*e^d over registers ----
        float S = 0.0f, T = 0.0f;
        #pragma unroll
        for (int k = 0; k < 8; k++) {
            if (ok[k]) {
                float d, e;
                d = v[k].x - rm; e = __expf(d); S += e; T = fmaf(d, e, T);
                d = v[k].y - rm; e = __expf(d); S += e; T = fmaf(d, e, T);
                d = v[k].z - rm; e = __expf(d); S += e; T = fmaf(d, e, T);
                d = v[k].w - rm; e = __expf(d); S += e; T = fmaf(d, e, T);
            }
        }
        #pragma unroll
        for (int o = 16; o > 0; o >>= 1) {
            S += __shfl_xor_sync(0xffffffffu, S, o);
            T += __shfl_xor_sync(0xffffffffu, T, o);
        }

        if (lane == 0) {
            int lbl = (int)labels[row];
            float zl = __ldg(&logits[(size_t)row * (size_t)C + lbl]); // L1 hit
            float conf = 1.0f / S;
            float logS = logf(S);
            float unc  = logS - T / S;              // entropy
            float ce   = (rm - zl) + logS;          // -log_softmax at label
            g_unc[row]     = unc;
            g_confacc[row] = (pred == lbl) ? conf : -conf;
            s_unc[wid] = unc;
            s_ce[wid]  = ce;
        }
    } else if (lane == 0) {
        s_unc[wid] = 0.0f;   // neutralized below via valid count
        s_ce[wid]  = 0.0f;
    }
    __syncthreads();

    // per-block reduce of WPB row stats -> 3 fire-and-forget atomics
    if (threadIdx.x == 0) {
        int valid = n - blockIdx.x * WPB;
        if (valid > WPB) valid = WPB;
        float mn = FLT_MAX, mx = -FLT_MAX, cs = 0.0f;
        for (int w = 0; w < valid; w++) {
            float u = s_unc[w];
            mn = fminf(mn, u);
            mx = fmaxf(mx, u);
            cs += s_ce[w];
        }
        atomicMin(&g_umin_bits, f2ord(mn));
        atomicMax(&g_umax_bits, f2ord(mx));
        atomicAdd(&g_cesum, cs);
    }
}

// ---------------- K2: cutoff histogram + fused final scalar ----------------
template <int BLK>
__global__ void __launch_bounds__(BLK)
k_bins(float* __restrict__ out, int n) {
    __shared__ float sb[88];
    __shared__ bool  is_last;
    if (threadIdx.x < 88) sb[threadIdx.x] = 0.0f;
    __syncthreads();

    const float umin  = ord2f(g_umin_bits);
    const float umax  = ord2f(g_umax_bits);
    const float range = umax - umin;

    for (int i = blockIdx.x * BLK + threadIdx.x; i < n; i += gridDim.x * BLK) {
        float unc = g_unc[i];
        float ca  = g_confacc[i];
        int acc   = (ca > 0.0f) ? 1 : 0;
        float conf = fabsf(ca);
        float w = acc ? conf : (1.0f - conf);
        // tanh(u), u >= 0:  1 - 2/(e^{2u}+1)   (one MUFU, no branches)
        float t = 1.0f - 2.0f / (__expf(2.0f * unc) + 1.0f);
        float bc = w * (1.0f - t);   // contribution if certain
        float bu = w * t;            // contribution if uncertain
        int j0 = 21;                 // smallest j with unc <= th_j (21 = never)
        #pragma unroll
        for (int j = 20; j >= 0; j--) {
            float thv = umin + (0.05f * (float)j) * range;
            if (unc <= thv) j0 = j;
        }
        atomicAdd(&sb[acc * 44 + j0], bc);
        atomicAdd(&sb[acc * 44 + 22 + j0], bu);
    }
    __syncthreads();
    if (threadIdx.x < 88) atomicAdd(&g_bins[threadIdx.x], sb[threadIdx.x]);

    // completion-counter fusion: last block computes the final scalar
    __threadfence();
    __syncthreads();
    if (threadIdx.x == 0) {
        unsigned int d = atomicAdd(&g_done, 1u);
        is_last = (d == gridDim.x - 1);
    }
    __syncthreads();
    if (is_last && threadIdx.x == 0) {
        float au_rem = 0.0f, iu_rem = 0.0f;
        for (int k = 0; k < 22; k++) {
            au_rem += g_bins[66 + k];   // acc=1, kind=U
            iu_rem += g_bins[22 + k];   // acc=0, kind=U
        }
        float nac = 0.0f, nic = 0.0f;
        float avu[21];
        for (int j = 0; j < 21; j++) {
            nac    += g_bins[44 + j];   // acc=1, kind=C prefix
            nic    += g_bins[j];        // acc=0, kind=C prefix
            au_rem -= g_bins[66 + j];
            iu_rem -= g_bins[22 + j];
            avu[j] = (nac + iu_rem) / (nac + au_rem + nic + iu_rem + 1e-12f);
        }
        float auc = 0.0f;
        for (int j = 0; j < 20; j++) auc += (avu[j + 1] + avu[j]);
        auc *= 0.5f * 0.05f;
        out[0] = -3.0f * logf(auc + 1e-12f) + g_cesum / (float)n;
    }
}

extern "C" void kernel_launch(void* const* d_in, const int* in_sizes, int n_in,
                              void* d_out, int out_size) {
    const float*     logits = (const float*)d_in[0];
    const long long* labels = (const long long*)d_in[1];
    int n = in_sizes[1];
    int C = in_sizes[0] / n;

    k_init<<<1, 128>>>();
    const int WPB = 8;                       // 256 threads, 8 rows per block
    k_rows<WPB><<<(n + WPB - 1) / WPB, WPB * 32>>>(logits, labels, C, n);
    k_bins<256><<<256, 256>>>((float*)d_out, n);
}